// round 8
// baseline (speedup 1.0000x reference)
#include <cuda_runtime.h>
#include <cstdint>

#define BB 1024
#define TT 256
#define EE 384
#define HH 64

// Scratch (no-allocation rule: __device__ globals).
__device__ float g_q[BB * TT * HH];
__device__ float g_k[BB * TT * HH];   // tf32-rounded, pair-permuted within 8-col groups
__device__ float g_v[BB * TT * HH];   // tf32-rounded
// W fused+transposed+k-permuted+tf32-rounded: [mat][n][k_perm], row = m*64+n.
__device__ float g_wt[3 * HH * EE];

// ---------------------------------------------------------------------------
// helpers
// ---------------------------------------------------------------------------
__device__ __forceinline__ float ex2f(float x) {
    float y;
    asm("ex2.approx.ftz.f32 %0, %1;" : "=f"(y) : "f"(x));
    return y;
}
__device__ __forceinline__ uint32_t tf32r(float f) {
    uint32_t r;
    asm("cvt.rna.tf32.f32 %0, %1;" : "=r"(r) : "f"(f));
    return r;
}
// m16n8k8 tf32 mma (baseline PTX, works on compute_103).
__device__ __forceinline__ void mma8(float* d, const uint32_t* a, uint32_t b0, uint32_t b1) {
    asm("mma.sync.aligned.m16n8k8.row.col.f32.tf32.tf32.f32 "
        "{%0,%1,%2,%3}, {%4,%5,%6,%7}, {%8,%9}, {%0,%1,%2,%3};"
        : "+f"(d[0]), "+f"(d[1]), "+f"(d[2]), "+f"(d[3])
        : "r"(a[0]), "r"(a[1]), "r"(a[2]), "r"(a[3]), "r"(b0), "r"(b1));
}
__device__ __forceinline__ void cpa16(uint32_t dst, const void* src) {
    asm volatile("cp.async.cg.shared.global [%0], [%1], 16;" :: "r"(dst), "l"(src));
}
__device__ __forceinline__ uint32_t smem_u32(const void* p) {
    uint32_t a;
    asm("{ .reg .u64 t; cvta.to.shared.u64 t, %1; cvt.u32.u64 %0, t; }" : "=r"(a) : "l"(p));
    return a;
}
__device__ __forceinline__ float shflx(float v, int m) {
    return __shfl_xor_sync(0xffffffffu, v, m);
}

// ---------------------------------------------------------------------------
// Kernel 0: build g_wt (pair-interleaved k within 8-groups, tf32-rounded).
// ---------------------------------------------------------------------------
__global__ void wt_kernel(const float* __restrict__ Wq, const float* __restrict__ Wk,
                          const float* __restrict__ Wv) {
    int idx = blockIdx.x * 256 + threadIdx.x;
    if (idx >= 3 * HH * EE) return;
    int m  = idx / (HH * EE);
    int n  = (idx / EE) & 63;
    int kp = idx % EE;
    int k  = (kp & ~7) + ((kp & 7) >> 1) + ((kp & 1) << 2);
    const float* W = (m == 0) ? Wq : (m == 1) ? Wk : Wv;
    uint32_t v = tf32r(W[k * HH + n]);
    g_wt[idx] = __uint_as_float(v);
}

// ---------------------------------------------------------------------------
// Kernel 1: QKV projection with mma.sync tf32 (as R5). Epilogue: q raw fp32;
// v tf32-rounded; k tf32-rounded AND pair-permuted within each 8-col group
// (phys p holds logical k=(p>>1)+((p&1)<<2)) so attn K b-frags are LDS.64.
// ---------------------------------------------------------------------------
#define QS_STAGE 51200
#define QS_WOFF  20480

__device__ __forceinline__ void qkv_load(uint32_t sbase, int stage, int chunk,
                                         const float* __restrict__ x, long long r0) {
    uint32_t xs = sbase + stage * QS_STAGE;
    uint32_t ws = xs + QS_WOFF;
    int tid = threadIdx.x;
#pragma unroll
    for (int i = 0; i < 4; i++) {                 // x: 128 rows x 32 f
        int idx = tid + i * 256;
        int row = idx >> 3, c16 = idx & 7;
        uint32_t doff = (uint32_t)(c16 * 16) ^ (uint32_t)((row & 4) << 2);
        cpa16(xs + row * 160 + doff, x + (r0 + row) * EE + chunk * 32 + c16 * 4);
    }
#pragma unroll
    for (int i = 0; i < 6; i++) {                 // W: 192 rows x 32 f
        int idx = tid + i * 256;
        int row = idx >> 3, c16 = idx & 7;
        cpa16(ws + row * 160 + c16 * 16, g_wt + row * EE + chunk * 32 + c16 * 4);
    }
}

__global__ void __launch_bounds__(256, 1) qkv_kernel(const float* __restrict__ x)
{
    extern __shared__ __align__(16) char smem[];
    uint32_t sbase = smem_u32(smem);
    int tid = threadIdx.x, wid = tid >> 5, lane = tid & 31;
    int g = lane >> 2, tig = lane & 3;
    int wm = wid >> 1, nh = wid & 1;
    int rb = wm * 32;
    long long r0 = (long long)blockIdx.x * 128;

    float acc[12][2][4];
#pragma unroll
    for (int nt = 0; nt < 12; nt++)
#pragma unroll
        for (int mt = 0; mt < 2; mt++)
#pragma unroll
            for (int i = 0; i < 4; i++) acc[nt][mt][i] = 0.f;

    qkv_load(sbase, 0, 0, x, r0);
    asm volatile("cp.async.commit_group;" ::: "memory");
    qkv_load(sbase, 1, 1, x, r0);
    asm volatile("cp.async.commit_group;" ::: "memory");

    for (int c = 0; c < 12; c++) {
        if (c < 11) asm volatile("cp.async.wait_group 1;" ::: "memory");
        else        asm volatile("cp.async.wait_group 0;" ::: "memory");
        __syncthreads();

        const float* xs = (const float*)(smem + (c & 1) * QS_STAGE);
        const float* ws = (const float*)(smem + (c & 1) * QS_STAGE + QS_WOFF);
#pragma unroll
        for (int ks = 0; ks < 4; ks++) {
            int kb = ks * 8;
            uint32_t A[2][4];
#pragma unroll
            for (int mt = 0; mt < 2; mt++) {
                int r_ = rb + mt * 16 + g;
                int sw = r_ & 4;                 // XOR swizzle bit
                A[mt][0] = tf32r(xs[r_ * 40 + ((kb + tig) ^ sw)]);
                A[mt][1] = tf32r(xs[(r_ + 8) * 40 + ((kb + tig) ^ sw)]);
                A[mt][2] = tf32r(xs[r_ * 40 + ((kb + tig + 4) ^ sw)]);
                A[mt][3] = tf32r(xs[(r_ + 8) * 40 + ((kb + tig + 4) ^ sw)]);
            }
#pragma unroll
            for (int nt = 0; nt < 12; nt++) {
                int brow = nh * 96 + nt * 8 + g;
                float2 bv = *(const float2*)&ws[brow * 40 + kb + 2 * tig];
                uint32_t b0 = __float_as_uint(bv.x), b1 = __float_as_uint(bv.y);
                mma8(acc[nt][0], A[0], b0, b1);
                mma8(acc[nt][1], A[1], b0, b1);
            }
        }
        __syncthreads();

        if (c + 2 < 12) {
            qkv_load(sbase, c & 1, c + 2, x, r0);
            asm volatile("cp.async.commit_group;" ::: "memory");
        }
    }

    float* const outs[3] = { g_q, g_k, g_v };
#pragma unroll
    for (int nt = 0; nt < 12; nt++) {
        int gc = nh * 96 + nt * 8;
        int mat = gc >> 6;
#pragma unroll
        for (int mt = 0; mt < 2; mt++) {
            long long row0 = r0 + rb + mt * 16 + g;
            float v0 = acc[nt][mt][0], v1 = acc[nt][mt][1];
            float v2 = acc[nt][mt][2], v3 = acc[nt][mt][3];
            if (mat != 0) {
                v0 = __uint_as_float(tf32r(v0)); v1 = __uint_as_float(tf32r(v1));
                v2 = __uint_as_float(tf32r(v2)); v3 = __uint_as_float(tf32r(v3));
            }
            if (mat == 1) {
                // permuted scalar stores: logical cols (2tig, 2tig+1) ->
                // phys (p0, p0+2), p0 = ((tig&1)<<2) + (tig>>1)
                int cb = gc & 63;
                int p0 = ((tig & 1) << 2) + (tig >> 1);
                float* o0 = g_k + cb + p0;
                o0[row0 * HH] = v0;       o0[row0 * HH + 2] = v1;
                o0[(row0 + 8) * HH] = v2; o0[(row0 + 8) * HH + 2] = v3;
            } else {
                float* op = outs[mat] + (gc & 63) + 2 * tig;
                *(float2*)(op + row0 * HH) = make_float2(v0, v1);
                *(float2*)(op + (row0 + 8) * HH) = make_float2(v2, v3);
            }
        }
    }
}

// ---------------------------------------------------------------------------
// Kernel 2: flash attention with mma.sync tf32.
// 1 CTA/batch, 512 threads / 16 warps. Warp w owns the single 16-row m-tile w
// (chunks-of-64 count = (w+4)>>2; per-SMSP totals are balanced at 10).
// smem: ks/vs [256][72] (K pair-permuted -> LDS.64 b-frags, conflict-free),
// per-warp P tile [16][68].
// ---------------------------------------------------------------------------
#define KVS 72
#define PST 68
#define ATTN_SMEM ((2 * 256 * KVS + 16 * 16 * PST) * 4)

__global__ void __launch_bounds__(512, 1) attn_kernel(float* __restrict__ out)
{
    extern __shared__ __align__(16) float sm[];
    float* ks = sm;                          // [256][72]
    float* vs = sm + 256 * KVS;              // [256][72]
    int b = blockIdx.x;
    int tid = threadIdx.x, w = tid >> 5, lane = tid & 31;
    int g = lane >> 2, tig = lane & 3;
    float* pw = sm + 2 * 256 * KVS + w * (16 * PST);

    // cooperative K/V fill (K already permuted + tf32 in global)
    {
        uint32_t ksu = smem_u32(ks);
        const float* kg = g_k + (size_t)b * TT * HH;
        const float* vg = g_v + (size_t)b * TT * HH;
#pragma unroll
        for (int i = 0; i < 8; i++) {
            int idx = tid + i * 512;          // 0..4095 float4s
            int key = idx >> 4, h4 = idx & 15;
            cpa16(ksu + (uint32_t)(key * KVS + h4 * 4) * 4, kg + key * 64 + h4 * 4);
            cpa16(ksu + (uint32_t)(256 * KVS + key * KVS + h4 * 4) * 4, vg + key * 64 + h4 * 4);
        }
        asm volatile("cp.async.commit_group;" ::: "memory");
    }

    // Q fragments, pre-scaled by 1/sqrt(H)*log2(e), tf32 (logical k indexing).
    const float scl = 0.125f * 1.44269504089f;
    int m0 = w * 16;
    uint32_t qf[8][4];
    const float* qg = g_q + (size_t)b * TT * HH;
#pragma unroll
    for (int kc = 0; kc < 8; kc++) {
        qf[kc][0] = tf32r(scl * qg[(m0 + g) * 64 + kc * 8 + tig]);
        qf[kc][1] = tf32r(scl * qg[(m0 + 8 + g) * 64 + kc * 8 + tig]);
        qf[kc][2] = tf32r(scl * qg[(m0 + g) * 64 + kc * 8 + tig + 4]);
        qf[kc][3] = tf32r(scl * qg[(m0 + 8 + g) * 64 + kc * 8 + tig + 4]);
    }

    asm volatile("cp.async.wait_group 0;" ::: "memory");
    __syncthreads();

    int nch = (w + 4) >> 2;                  // chunks of 64 keys
    float o[8][4];
#pragma unroll
    for (int nt = 0; nt < 8; nt++)
#pragma unroll
        for (int e = 0; e < 4; e++) o[nt][e] = 0.f;
    float mr0 = -INFINITY, mr1 = -INFINITY, l0 = 0.f, l1 = 0.f;

    for (int ci = 0; ci < nch; ci++) {
        int kc0 = ci * 64;
        // ---- QK^T: S[16][64] (K b-frag = one LDS.64, phys pair = logical (tig, tig+4)) ----
        float s[8][4];
#pragma unroll
        for (int nt = 0; nt < 8; nt++)
#pragma unroll
            for (int e = 0; e < 4; e++) s[nt][e] = 0.f;
#pragma unroll
        for (int kc = 0; kc < 8; kc++) {
#pragma unroll
            for (int nt = 0; nt < 8; nt++) {
                float2 bv = *(const float2*)(ks + (kc0 + nt * 8 + g) * KVS + kc * 8 + 2 * tig);
                mma8(s[nt], qf[kc], __float_as_uint(bv.x), __float_as_uint(bv.y));
            }
        }
        // ---- causal mask (warp-uniform branch) ----
        if (kc0 + 63 > m0) {
            int r0_ = m0 + g, r1_ = m0 + 8 + g;
#pragma unroll
            for (int nt = 0; nt < 8; nt++) {
                int k0_ = kc0 + nt * 8 + 2 * tig;
                s[nt][0] = (k0_     <= r0_) ? s[nt][0] : -INFINITY;
                s[nt][1] = (k0_ + 1 <= r0_) ? s[nt][1] : -INFINITY;
                s[nt][2] = (k0_     <= r1_) ? s[nt][2] : -INFINITY;
                s[nt][3] = (k0_ + 1 <= r1_) ? s[nt][3] : -INFINITY;
            }
        }
        // ---- online softmax (base-2) ----
        float mx0 = s[0][0], mx1 = s[0][2];
#pragma unroll
        for (int nt = 0; nt < 8; nt++) {
            mx0 = fmaxf(mx0, fmaxf(s[nt][0], s[nt][1]));
            mx1 = fmaxf(mx1, fmaxf(s[nt][2], s[nt][3]));
        }
        mx0 = fmaxf(mx0, shflx(mx0, 1)); mx0 = fmaxf(mx0, shflx(mx0, 2));
        mx1 = fmaxf(mx1, shflx(mx1, 1)); mx1 = fmaxf(mx1, shflx(mx1, 2));
        float mn0 = fmaxf(mr0, mx0), mn1 = fmaxf(mr1, mx1);
        float c0 = ex2f(mr0 - mn0), c1 = ex2f(mr1 - mn1);
        mr0 = mn0; mr1 = mn1;
        float p0 = 0.f, p1 = 0.f;
#pragma unroll
        for (int nt = 0; nt < 8; nt++) {
            s[nt][0] = ex2f(s[nt][0] - mr0);
            s[nt][1] = ex2f(s[nt][1] - mr0);
            s[nt][2] = ex2f(s[nt][2] - mr1);
            s[nt][3] = ex2f(s[nt][3] - mr1);
            p0 += s[nt][0] + s[nt][1];
            p1 += s[nt][2] + s[nt][3];
        }
        p0 += shflx(p0, 1); p0 += shflx(p0, 2);
        p1 += shflx(p1, 1); p1 += shflx(p1, 2);
        l0 = l0 * c0 + p0;
        l1 = l1 * c1 + p1;
#pragma unroll
        for (int nt = 0; nt < 8; nt++) {
            o[nt][0] *= c0; o[nt][1] *= c0;
            o[nt][2] *= c1; o[nt][3] *= c1;
        }
        // ---- stage P (tf32-rounded) ----
        __syncwarp();
#pragma unroll
        for (int nt = 0; nt < 8; nt++) {
            int cb = nt * 8 + 2 * tig;
            *(float2*)&pw[g * PST + cb] =
                make_float2(__uint_as_float(tf32r(s[nt][0])), __uint_as_float(tf32r(s[nt][1])));
            *(float2*)&pw[(8 + g) * PST + cb] =
                make_float2(__uint_as_float(tf32r(s[nt][2])), __uint_as_float(tf32r(s[nt][3])));
        }
        __syncwarp();
        // ---- P @ V ----
#pragma unroll
        for (int kc2 = 0; kc2 < 8; kc2++) {
            uint32_t pa[4];
            pa[0] = __float_as_uint(pw[g * PST + kc2 * 8 + tig]);
            pa[1] = __float_as_uint(pw[(8 + g) * PST + kc2 * 8 + tig]);
            pa[2] = __float_as_uint(pw[g * PST + kc2 * 8 + tig + 4]);
            pa[3] = __float_as_uint(pw[(8 + g) * PST + kc2 * 8 + tig + 4]);
            const float* v0p = vs + (kc0 + kc2 * 8 + tig) * KVS;
            const float* v1p = vs + (kc0 + kc2 * 8 + tig + 4) * KVS;
#pragma unroll
            for (int nt2 = 0; nt2 < 8; nt2++) {
                uint32_t b0 = __float_as_uint(v0p[nt2 * 8 + g]);
                uint32_t b1 = __float_as_uint(v1p[nt2 * 8 + g]);
                mma8(o[nt2], pa, b0, b1);
            }
        }
        __syncwarp();
    }

    // ---- normalize + store ----
    float inv0 = 1.0f / l0, inv1 = 1.0f / l1;
    float* ob = out + ((size_t)b * TT + m0) * HH;
#pragma unroll
    for (int nt = 0; nt < 8; nt++) {
        int cb = nt * 8 + 2 * tig;
        *(float2*)(ob + g * 64 + cb) = make_float2(o[nt][0] * inv0, o[nt][1] * inv0);
        *(float2*)(ob + (8 + g) * 64 + cb) = make_float2(o[nt][2] * inv1, o[nt][3] * inv1);
    }
}

extern "C" void kernel_launch(void* const* d_in, const int* in_sizes, int n_in,
                              void* d_out, int out_size)
{
    (void)in_sizes; (void)n_in; (void)out_size;
    const float* x  = (const float*)d_in[0];
    const float* Wq = (const float*)d_in[1];
    const float* Wk = (const float*)d_in[2];
    const float* Wv = (const float*)d_in[3];
    float* out = (float*)d_out;

    const int qkv_smem = 2 * QS_STAGE;                        // 100 KB
    cudaFuncSetAttribute(qkv_kernel, cudaFuncAttributeMaxDynamicSharedMemorySize, qkv_smem);
    cudaFuncSetAttribute(attn_kernel, cudaFuncAttributeMaxDynamicSharedMemorySize, ATTN_SMEM);

    wt_kernel<<<(3 * HH * EE + 255) / 256, 256>>>(Wq, Wk, Wv);
    qkv_kernel<<<(BB * TT) / 128, 256, qkv_smem>>>(x);
    attn_kernel<<<BB, 512, ATTN_SMEM>>>(out);
}